// round 16
// baseline (speedup 1.0000x reference)
#include <cuda_runtime.h>
#include <cuda_bf16.h>
#include <cstdint>

#define NN 100000
#define EE 1600000
#define FF 128
#define RR 50
#define BN_EPS 1e-3f
#define BIASF 8421376.0f   // 2^23 + 32768

// Scratch (allocation-free rule: device globals)
__device__ float g_h[(size_t)NN * FF];     // batchnormed features (fp32, self-term)
__device__ unsigned short g_hq[(size_t)NN * FF];  // h quantized: biased uint16
__device__ float g_hs[NN];                 // per-row quant scale
__device__ float g_pre[(size_t)NN * FF];   // coeff-residual + aggregated messages
__device__ int   g_deg[NN];
__device__ int   g_rowptr[NN + 1];
__device__ int   g_cursor[NN];
__device__ int2  g_cpack[EE];              // (col, w'_bits) per CSR slot
__device__ int   g_blocksum[64];
__device__ unsigned short g_wt_hi[FF * FF];  // W^T hi, [n][k] row-major bf16
__device__ unsigned short g_wt_lo[FF * FF];  // W^T lo, [n][k] row-major bf16

// ---------------------------------------------------------------------------
__device__ __forceinline__ uint32_t smem_u32(const void* p) {
    uint32_t a;
    asm("{ .reg .u64 t; cvta.to.shared.u64 t, %1; cvt.u32.u64 %0, t; }"
        : "=r"(a) : "l"(p));
    return a;
}
__device__ __forceinline__ uint32_t pack_bf2(float a, float b) {
    __nv_bfloat162 h2 = __floats2bfloat162_rn(a, b);
    uint32_t u; memcpy(&u, &h2, 4);
    return u;
}
// dequant: biased uint16 (in low/high half of u) -> float value (q - 32768)
__device__ __forceinline__ float dq_lo(uint32_t u) {
    return __uint_as_float(__byte_perm(u, 0x4B000000u, 0x7410)) - BIASF;
}
__device__ __forceinline__ float dq_hi(uint32_t u) {
    return __uint_as_float(__byte_perm(u, 0x4B000000u, 0x7432)) - BIASF;
}

// ---------------------------------------------------------------------------
// Kernel 1: BatchNorm into g_h (fp32) + int16 row-quantized image + scale;
// also zero g_deg. One warp == one row (idx = row*32 + c4).
// ---------------------------------------------------------------------------
__global__ void __launch_bounds__(256)
bn_kernel(const float* __restrict__ x,
          const float* __restrict__ gamma,
          const float* __restrict__ beta,
          const float* __restrict__ mean,
          const float* __restrict__ var)
{
    __shared__ float s_scale[FF], s_shift[FF];
    int tid = threadIdx.x;
    if (tid < FF) {
        float sc = gamma[tid] * rsqrtf(var[tid] + BN_EPS);
        s_scale[tid] = sc;
        s_shift[tid] = beta[tid] - mean[tid] * sc;
    }
    __syncthreads();

    int idx = blockIdx.x * blockDim.x + tid;
    if (idx < NN) g_deg[idx] = 0;
    if (idx >= NN * (FF / 4)) return;

    int c = (idx & 31) * 4;
    float4 xv = ((const float4*)x)[idx];
    float4 hv;
    hv.x = xv.x * s_scale[c + 0] + s_shift[c + 0];
    hv.y = xv.y * s_scale[c + 1] + s_shift[c + 1];
    hv.z = xv.z * s_scale[c + 2] + s_shift[c + 2];
    hv.w = xv.w * s_scale[c + 3] + s_shift[c + 3];
    ((float4*)g_h)[idx] = hv;

    // warp row-max reduce and int16 quantize
    float m = fmaxf(fmaxf(fabsf(hv.x), fabsf(hv.y)),
                    fmaxf(fabsf(hv.z), fabsf(hv.w)));
#pragma unroll
    for (int d = 16; d >= 1; d >>= 1)
        m = fmaxf(m, __shfl_xor_sync(0xffffffffu, m, d));

    float inv = 32767.0f / fmaxf(m, 1e-30f);
    int q0 = __float2int_rn(hv.x * inv) + 32768;
    int q1 = __float2int_rn(hv.y * inv) + 32768;
    int q2 = __float2int_rn(hv.z * inv) + 32768;
    int q3 = __float2int_rn(hv.w * inv) + 32768;
    uint2 qu;
    qu.x = (uint32_t)q0 | ((uint32_t)q1 << 16);
    qu.y = (uint32_t)q2 | ((uint32_t)q3 << 16);
    ((uint2*)g_hq)[idx] = qu;
    if ((tid & 31) == 0) g_hs[idx >> 5] = m * (1.0f / 32767.0f);
}

// ---------------------------------------------------------------------------
// Kernel W-prep: split W^T into bf16 hi/lo row-major [n][k] images.
// ---------------------------------------------------------------------------
__global__ void wprep_kernel(const float* __restrict__ W)
{
    int idx = blockIdx.x * blockDim.x + threadIdx.x;
    if (idx >= FF * FF) return;
    int n = idx >> 7, k = idx & 127;
    float v = W[k * FF + n];
    __nv_bfloat16 hb = __float2bfloat16(v);
    float lo = v - __bfloat162float(hb);
    __nv_bfloat16 lb = __float2bfloat16(lo);
    unsigned short hu, lu;
    memcpy(&hu, &hb, 2); memcpy(&lu, &lb, 2);
    g_wt_hi[idx] = hu;
    g_wt_lo[idx] = lu;
}

// ---------------------------------------------------------------------------
// Kernel 2: degree histogram
// ---------------------------------------------------------------------------
__global__ void hist_kernel(const int* __restrict__ rows)
{
    int e = blockIdx.x * blockDim.x + threadIdx.x;
    if (e < EE) atomicAdd(&g_deg[rows[e]], 1);
}

// ---------------------------------------------------------------------------
// Kernel 3a: block-local exclusive scan. 25 blocks x 256 thr x 16 elems.
// ---------------------------------------------------------------------------
#define SCB 4096
#define SCAN_BLOCKS ((NN + SCB - 1) / SCB)   // 25

__global__ void __launch_bounds__(256)
scan_blocks_kernel()
{
    __shared__ int sh[SCB];
    __shared__ int warpsums[8];
    int b = blockIdx.x, t = threadIdx.x;
    int base = b * SCB;

#pragma unroll
    for (int i = 0; i < 16; i++) {
        int idx = base + i * 256 + t;
        sh[i * 256 + t] = (idx < NN) ? g_deg[idx] : 0;
    }
    __syncthreads();

    int o = t * 16;
    int my = 0;
#pragma unroll
    for (int i = 0; i < 16; i++) my += sh[o + i];

    int lane = t & 31, wid = t >> 5;
    int pref = my;
#pragma unroll
    for (int d = 1; d < 32; d <<= 1) {
        int v = __shfl_up_sync(0xffffffffu, pref, d);
        if (lane >= d) pref += v;
    }
    if (lane == 31) warpsums[wid] = pref;
    __syncthreads();

    int woff = 0;
#pragma unroll
    for (int i = 0; i < 8; i++)
        if (i < wid) woff += warpsums[i];

    int run = woff + pref - my;
#pragma unroll
    for (int i = 0; i < 16; i++) {
        int v = sh[o + i];
        sh[o + i] = run;
        run += v;
    }
    if (t == 255) g_blocksum[b] = run;
    __syncthreads();

#pragma unroll
    for (int i = 0; i < 16; i++) {
        int idx = base + i * 256 + t;
        if (idx < NN) g_rowptr[idx] = sh[i * 256 + t];
    }
}

// ---------------------------------------------------------------------------
// Kernel 3b: add block offsets; init cursors; set rowptr[NN].
// ---------------------------------------------------------------------------
__global__ void __launch_bounds__(256)
scan_addoff_kernel()
{
    __shared__ int soff[32];
    int t = threadIdx.x;
    if (t < 32) {
        int v = (t < SCAN_BLOCKS) ? g_blocksum[t] : 0;
        int p = v;
#pragma unroll
        for (int d = 1; d < 32; d <<= 1) {
            int u = __shfl_up_sync(0xffffffffu, p, d);
            if (t >= d) p += u;
        }
        soff[t] = p - v;
    }
    __syncthreads();

    int i = blockIdx.x * blockDim.x + t;
    if (i < NN) {
        int v = g_rowptr[i] + soff[i >> 12];
        g_rowptr[i] = v;
        g_cursor[i] = v;
    }
    if (i == 0) g_rowptr[NN] = EE;
}

// ---------------------------------------------------------------------------
// Kernel 4: fill CSR slots; weight pre-multiplied by the source row's
// dequant scale: w' = vals/(rc+1) * g_hs[col].
// ---------------------------------------------------------------------------
__global__ void fill_kernel(const int*   __restrict__ rows,
                            const int*   __restrict__ cols,
                            const float* __restrict__ vals,
                            const int*   __restrict__ rels,
                            const float* __restrict__ rc)
{
    int e = blockIdx.x * blockDim.x + threadIdx.x;
    if (e >= EE) return;
    int r = rows[e];
    int c = cols[e];
    float w = vals[e] / (rc[rels[e]] + 1.0f) * __ldg(&g_hs[c]);
    int pos = atomicAdd(&g_cursor[r], 1);
    int2 p;
    p.x = c;
    p.y = __float_as_int(w);
    g_cpack[pos] = p;
}

// ---------------------------------------------------------------------------
// Kernel 5: SpMM-CSR, warp/node, 8-wide unroll, int16-quantized gather
// (halved L2 traffic). msg = w' * (q - 32768); dequant via PRMT+FADD (exact).
// ---------------------------------------------------------------------------
__global__ void __launch_bounds__(256)
spmm_csr_kernel(const float* __restrict__ coeff)
{
    int lane = threadIdx.x & 31;
    int node = blockIdx.x * (blockDim.x >> 5) + (threadIdx.x >> 5);
    if (node >= NN) return;

    const float4* hrow = (const float4*)(g_h + (size_t)node * FF);
    float4 hv = hrow[lane];
    float cm = coeff[node] + 1.0f;
    float ax = hv.x * cm, ay = hv.y * cm, az = hv.z * cm, aw = hv.w * cm;

    const uint2* hq = (const uint2*)g_hq;   // 32 uint2 per row

    int p   = g_rowptr[node];
    int end = g_rowptr[node + 1];

    for (; p + 8 <= end; p += 8) {
        int2 e0 = g_cpack[p + 0], e1 = g_cpack[p + 1];
        int2 e2 = g_cpack[p + 2], e3 = g_cpack[p + 3];
        int2 e4 = g_cpack[p + 4], e5 = g_cpack[p + 5];
        int2 e6 = g_cpack[p + 6], e7 = g_cpack[p + 7];
        uint2 u0 = __ldg(hq + (size_t)e0.x * 32 + lane);
        uint2 u1 = __ldg(hq + (size_t)e1.x * 32 + lane);
        uint2 u2 = __ldg(hq + (size_t)e2.x * 32 + lane);
        uint2 u3 = __ldg(hq + (size_t)e3.x * 32 + lane);
        uint2 u4 = __ldg(hq + (size_t)e4.x * 32 + lane);
        uint2 u5 = __ldg(hq + (size_t)e5.x * 32 + lane);
        uint2 u6 = __ldg(hq + (size_t)e6.x * 32 + lane);
        uint2 u7 = __ldg(hq + (size_t)e7.x * 32 + lane);
        float w0 = __int_as_float(e0.y), w1 = __int_as_float(e1.y);
        float w2 = __int_as_float(e2.y), w3 = __int_as_float(e3.y);
        float w4 = __int_as_float(e4.y), w5 = __int_as_float(e5.y);
        float w6 = __int_as_float(e6.y), w7 = __int_as_float(e7.y);
        ax += w0*dq_lo(u0.x) + w1*dq_lo(u1.x) + w2*dq_lo(u2.x) + w3*dq_lo(u3.x)
            + w4*dq_lo(u4.x) + w5*dq_lo(u5.x) + w6*dq_lo(u6.x) + w7*dq_lo(u7.x);
        ay += w0*dq_hi(u0.x) + w1*dq_hi(u1.x) + w2*dq_hi(u2.x) + w3*dq_hi(u3.x)
            + w4*dq_hi(u4.x) + w5*dq_hi(u5.x) + w6*dq_hi(u6.x) + w7*dq_hi(u7.x);
        az += w0*dq_lo(u0.y) + w1*dq_lo(u1.y) + w2*dq_lo(u2.y) + w3*dq_lo(u3.y)
            + w4*dq_lo(u4.y) + w5*dq_lo(u5.y) + w6*dq_lo(u6.y) + w7*dq_lo(u7.y);
        aw += w0*dq_hi(u0.y) + w1*dq_hi(u1.y) + w2*dq_hi(u2.y) + w3*dq_hi(u3.y)
            + w4*dq_hi(u4.y) + w5*dq_hi(u5.y) + w6*dq_hi(u6.y) + w7*dq_hi(u7.y);
    }
    for (; p < end; p++) {
        int2 e0 = g_cpack[p];
        uint2 u0 = __ldg(hq + (size_t)e0.x * 32 + lane);
        float w0 = __int_as_float(e0.y);
        ax += w0 * dq_lo(u0.x); ay += w0 * dq_hi(u0.x);
        az += w0 * dq_lo(u0.y); aw += w0 * dq_hi(u0.y);
    }

    ((float4*)(g_pre + (size_t)node * FF))[lane] = make_float4(ax, ay, az, aw);
}

// ---------------------------------------------------------------------------
// Kernel 6: tensor-core GEMM via mma.sync m16n8k16 bf16, 2-way split (R14).
// ---------------------------------------------------------------------------
#define WT_STRIDE 136
#define ROW_BYTES (WT_STRIDE * 2)           // 272
#define SM_AHI 0
#define SM_ALO (SM_AHI + 128 * ROW_BYTES)
#define SM_BHI (SM_ALO + 128 * ROW_BYTES)
#define SM_BLO (SM_BHI + 128 * ROW_BYTES)
#define SM_TOT (SM_BLO + 128 * ROW_BYTES)   // 139264

#define LDSM4(r0, r1, r2, r3, a) \
    asm volatile("ldmatrix.sync.aligned.m8n8.x4.shared.b16 {%0,%1,%2,%3}, [%4];" \
                 : "=r"(r0), "=r"(r1), "=r"(r2), "=r"(r3) : "r"(a))

#define MMA16816(c, a, b) \
    asm volatile("mma.sync.aligned.m16n8k16.row.col.f32.bf16.bf16.f32 " \
                 "{%0,%1,%2,%3}, {%4,%5,%6,%7}, {%8,%9}, {%0,%1,%2,%3};" \
                 : "+f"((c)[0]), "+f"((c)[1]), "+f"((c)[2]), "+f"((c)[3]) \
                 : "r"((a)[0]), "r"((a)[1]), "r"((a)[2]), "r"((a)[3]), \
                   "r"((b)[0]), "r"((b)[1]))

__global__ void __launch_bounds__(256)
gemm_mma_kernel(const float* __restrict__ bias, float* __restrict__ out)
{
    extern __shared__ char smem[];
    uint32_t sb = smem_u32(smem);
    int tid  = threadIdx.x;
    int warp = tid >> 5;
    int lane = tid & 31;
    int row0 = blockIdx.x * 128;

    // B tiles: straight copies
    for (int i = tid; i < 128 * 16; i += 256) {
        int r = i >> 4, c = i & 15;
        *(uint4*)(smem + SM_BHI + r * ROW_BYTES + c * 16) = ((const uint4*)g_wt_hi)[i];
        *(uint4*)(smem + SM_BLO + r * ROW_BYTES + c * 16) = ((const uint4*)g_wt_lo)[i];
    }

    // A convert: thread t -> row t>>1, k-half (t&1)*64
    {
        int lr = tid >> 1;
        int k0 = (tid & 1) * 64;
        int grow = row0 + lr;
        bool valid = (grow < NN);
        const float4* src = (const float4*)(g_pre + (size_t)grow * FF + k0);
        char* dhi = smem + SM_AHI + lr * ROW_BYTES + k0 * 2;
        char* dlo = smem + SM_ALO + lr * ROW_BYTES + k0 * 2;
#pragma unroll
        for (int j = 0; j < 16; j++) {
            float4 v = valid ? __ldg(src + j) : make_float4(0.f, 0.f, 0.f, 0.f);
            float hx = __bfloat162float(__float2bfloat16(v.x));
            float hy = __bfloat162float(__float2bfloat16(v.y));
            float hz = __bfloat162float(__float2bfloat16(v.z));
            float hw = __bfloat162float(__float2bfloat16(v.w));
            *(uint32_t*)(dhi + j * 8)     = pack_bf2(v.x, v.y);
            *(uint32_t*)(dhi + j * 8 + 4) = pack_bf2(v.z, v.w);
            *(uint32_t*)(dlo + j * 8)     = pack_bf2(v.x - hx, v.y - hy);
            *(uint32_t*)(dlo + j * 8 + 4) = pack_bf2(v.z - hz, v.w - hw);
        }
    }
    __syncthreads();

    int wm = warp >> 1;
    int wn = warp & 1;
    int arow = wm * 32;
    int bcol = wn * 64;

    float acc[2][8][4];
#pragma unroll
    for (int mt = 0; mt < 2; mt++)
#pragma unroll
        for (int nt = 0; nt < 8; nt++)
#pragma unroll
            for (int q = 0; q < 4; q++)
                acc[mt][nt][q] = 0.f;

    int a_r = lane & 15;
    int a_c = (lane >> 4) * 8;
    int b_r = ((lane >> 4) << 3) + (lane & 7);
    int b_c = ((lane >> 3) & 1) * 8;

#pragma unroll 1
    for (int ks = 0; ks < 8; ks++) {
        int kk = ks * 16;

        uint32_t ahi[2][4], alo[2][4];
#pragma unroll
        for (int mt = 0; mt < 2; mt++) {
            uint32_t off = (uint32_t)((arow + mt * 16 + a_r) * ROW_BYTES + (kk + a_c) * 2);
            LDSM4(ahi[mt][0], ahi[mt][1], ahi[mt][2], ahi[mt][3], sb + SM_AHI + off);
            LDSM4(alo[mt][0], alo[mt][1], alo[mt][2], alo[mt][3], sb + SM_ALO + off);
        }

        uint32_t bhi[8][2], blo[8][2];
#pragma unroll
        for (int g = 0; g < 4; g++) {
            uint32_t off = (uint32_t)((bcol + g * 16 + b_r) * ROW_BYTES + (kk + b_c) * 2);
            uint32_t r0, r1, r2, r3;
            LDSM4(r0, r1, r2, r3, sb + SM_BHI + off);
            bhi[g * 2 + 0][0] = r0; bhi[g * 2 + 0][1] = r1;
            bhi[g * 2 + 1][0] = r2; bhi[g * 2 + 1][1] = r3;
            LDSM4(r0, r1, r2, r3, sb + SM_BLO + off);
            blo[g * 2 + 0][0] = r0; blo[g * 2 + 0][1] = r1;
            blo[g * 2 + 1][0] = r2; blo[g * 2 + 1][1] = r3;
        }

#pragma unroll
        for (int mt = 0; mt < 2; mt++)
#pragma unroll
            for (int nt = 0; nt < 8; nt++) {
                MMA16816(acc[mt][nt], ahi[mt], bhi[nt]);
                MMA16816(acc[mt][nt], ahi[mt], blo[nt]);
                MMA16816(acc[mt][nt], alo[mt], bhi[nt]);
            }
    }

#pragma unroll
    for (int mt = 0; mt < 2; mt++) {
        int r_lo = row0 + arow + mt * 16 + (lane >> 2);
        int r_hi = r_lo + 8;
#pragma unroll
        for (int nt = 0; nt < 8; nt++) {
            int col = bcol + nt * 8 + (lane & 3) * 2;
            float2 bv = __ldg((const float2*)(bias + col));
            if (r_lo < NN) {
                float2 v0 = make_float2(acc[mt][nt][0] + bv.x, acc[mt][nt][1] + bv.y);
                *(float2*)(out + (size_t)r_lo * FF + col) = v0;
            }
            if (r_hi < NN) {
                float2 v1 = make_float2(acc[mt][nt][2] + bv.x, acc[mt][nt][3] + bv.y);
                *(float2*)(out + (size_t)r_hi * FF + col) = v1;
            }
        }
    }
}

// ---------------------------------------------------------------------------
extern "C" void kernel_launch(void* const* d_in, const int* in_sizes, int n_in,
                              void* d_out, int out_size)
{
    const float* x          = (const float*)d_in[0];
    const int*   edge_rows  = (const int*)  d_in[1];
    const int*   edge_cols  = (const int*)  d_in[2];
    const float* edge_vals  = (const float*)d_in[3];
    const int*   rel_ids    = (const int*)  d_in[4];
    const float* rel_coeffs = (const float*)d_in[5];
    const float* coeff_k    = (const float*)d_in[6];
    const float* dense_W    = (const float*)d_in[7];
    const float* dense_b    = (const float*)d_in[8];
    const float* bn_gamma   = (const float*)d_in[9];
    const float* bn_beta    = (const float*)d_in[10];
    const float* bn_mean    = (const float*)d_in[11];
    const float* bn_var     = (const float*)d_in[12];
    float*       out        = (float*)d_out;

    // 1) BN -> g_h + int16 quant image + zero deg
    {
        int total = NN * (FF / 4);
        bn_kernel<<<(total + 255) / 256, 256>>>(x, bn_gamma, bn_beta, bn_mean, bn_var);
    }
    // 1b) W split prep
    wprep_kernel<<<64, 256>>>(dense_W);
    // 2) degree histogram
    hist_kernel<<<(EE + 255) / 256, 256>>>(edge_rows);
    // 3) exclusive scan
    scan_blocks_kernel<<<SCAN_BLOCKS, 256>>>();
    scan_addoff_kernel<<<(NN + 255) / 256, 256>>>();
    // 4) CSR fill (weight folded with dequant scale)
    fill_kernel<<<(EE + 255) / 256, 256>>>(edge_rows, edge_cols, edge_vals,
                                           rel_ids, rel_coeffs);
    // 5) SpMM-CSR + coeff residual (int16 gather)
    spmm_csr_kernel<<<(NN + 7) / 8, 256>>>(coeff_k);
    // 6) Tensor-core GEMM
    {
        cudaFuncSetAttribute(gemm_mma_kernel,
                             cudaFuncAttributeMaxDynamicSharedMemorySize, SM_TOT);
        gemm_mma_kernel<<<(NN + 127) / 128, 256, SM_TOT>>>(dense_b, out);
    }
}

// round 17
// speedup vs baseline: 1.5525x; 1.5525x over previous
#include <cuda_runtime.h>
#include <cuda_bf16.h>
#include <cstdint>

#define NN 100000
#define EE 1600000
#define FF 128
#define RR 50
#define BN_EPS 1e-3f

// Scratch (allocation-free rule: device globals; zero-initialized at load,
// and restored to zero by the pipeline itself for graph replays)
__device__ float g_h[(size_t)NN * FF];     // batchnormed features
__device__ float g_pre[(size_t)NN * FF];   // coeff-residual + aggregated messages
__device__ int   g_deg[NN];                // per-row edge count (re-zeroed by spmm)
__device__ int   g_rowlocal[NN];           // block-local exclusive scan
__device__ int   g_cnt[NN];                // fill cursors, start 0 (re-zeroed by spmm)
__device__ int2  g_cpack[EE];              // (col, w_bits) per CSR slot
__device__ int   g_blocksum[32];           // per-scan-block totals
__device__ int   g_blockoff[32];           // scanned block offsets
__device__ int   g_done;                   // scan last-block ticket (self-resetting)
__device__ unsigned short g_wt_hi[FF * FF];  // W^T hi, [n][k] row-major bf16
__device__ unsigned short g_wt_lo[FF * FF];  // W^T lo, [n][k] row-major bf16

// ---------------------------------------------------------------------------
__device__ __forceinline__ uint32_t smem_u32(const void* p) {
    uint32_t a;
    asm("{ .reg .u64 t; cvta.to.shared.u64 t, %1; cvt.u32.u64 %0, t; }"
        : "=r"(a) : "l"(p));
    return a;
}
__device__ __forceinline__ uint32_t pack_bf2(float a, float b) {
    __nv_bfloat162 h2 = __floats2bfloat162_rn(a, b);
    uint32_t u; memcpy(&u, &h2, 4);
    return u;
}

// ---------------------------------------------------------------------------
// Launch 1 (FUSED): bn (blocks [0, BN_BLOCKS)), wprep, hist — all independent.
// ---------------------------------------------------------------------------
#define BN_BLOCKS 12500
#define WPREP_BLOCKS 64
#define HIST_BLOCKS ((EE + 255) / 256)     // 6250
#define FUSED_BLOCKS (BN_BLOCKS + WPREP_BLOCKS + HIST_BLOCKS)

__global__ void __launch_bounds__(256)
fused_front_kernel(const float* __restrict__ x,
                   const float* __restrict__ gamma,
                   const float* __restrict__ beta,
                   const float* __restrict__ mean,
                   const float* __restrict__ var,
                   const float* __restrict__ W,
                   const int*   __restrict__ rows)
{
    int tid = threadIdx.x;
    int b = blockIdx.x;

    if (b < BN_BLOCKS) {
        // ---- BatchNorm into g_h ----
        __shared__ float s_scale[FF], s_shift[FF];
        if (tid < FF) {
            float sc = gamma[tid] * rsqrtf(var[tid] + BN_EPS);
            s_scale[tid] = sc;
            s_shift[tid] = beta[tid] - mean[tid] * sc;
        }
        __syncthreads();

        int idx = b * 256 + tid;
        if (idx >= NN * (FF / 4)) return;
        int c = (idx & 31) * 4;
        float4 xv = ((const float4*)x)[idx];
        float4 hv;
        hv.x = xv.x * s_scale[c + 0] + s_shift[c + 0];
        hv.y = xv.y * s_scale[c + 1] + s_shift[c + 1];
        hv.z = xv.z * s_scale[c + 2] + s_shift[c + 2];
        hv.w = xv.w * s_scale[c + 3] + s_shift[c + 3];
        ((float4*)g_h)[idx] = hv;
    } else if (b < BN_BLOCKS + WPREP_BLOCKS) {
        // ---- W split prep ----
        int idx = (b - BN_BLOCKS) * 256 + tid;
        if (idx < FF * FF) {
            int n = idx >> 7, k = idx & 127;
            float v = W[k * FF + n];
            __nv_bfloat16 hb = __float2bfloat16(v);
            float lo = v - __bfloat162float(hb);
            __nv_bfloat16 lb = __float2bfloat16(lo);
            unsigned short hu, lu;
            memcpy(&hu, &hb, 2); memcpy(&lu, &lb, 2);
            g_wt_hi[idx] = hu;
            g_wt_lo[idx] = lu;
        }
    } else {
        // ---- degree histogram (g_deg is zero: static init / re-zeroed by spmm) ----
        int e = (b - BN_BLOCKS - WPREP_BLOCKS) * 256 + tid;
        if (e < EE) atomicAdd(&g_deg[rows[e]], 1);
    }
}

// ---------------------------------------------------------------------------
// Launch 2: block-local exclusive scan + last-block computes block offsets.
// ---------------------------------------------------------------------------
#define SCB 4096
#define SCAN_BLOCKS ((NN + SCB - 1) / SCB)   // 25

__global__ void __launch_bounds__(256)
scan_kernel()
{
    __shared__ int sh[SCB];
    __shared__ int warpsums[8];
    __shared__ int s_last;
    int b = blockIdx.x, t = threadIdx.x;
    int base = b * SCB;

#pragma unroll
    for (int i = 0; i < 16; i++) {
        int idx = base + i * 256 + t;
        sh[i * 256 + t] = (idx < NN) ? g_deg[idx] : 0;
    }
    __syncthreads();

    int o = t * 16;
    int my = 0;
#pragma unroll
    for (int i = 0; i < 16; i++) my += sh[o + i];

    int lane = t & 31, wid = t >> 5;
    int pref = my;
#pragma unroll
    for (int d = 1; d < 32; d <<= 1) {
        int v = __shfl_up_sync(0xffffffffu, pref, d);
        if (lane >= d) pref += v;
    }
    if (lane == 31) warpsums[wid] = pref;
    __syncthreads();

    int woff = 0;
#pragma unroll
    for (int i = 0; i < 8; i++)
        if (i < wid) woff += warpsums[i];

    int run = woff + pref - my;
#pragma unroll
    for (int i = 0; i < 16; i++) {
        int v = sh[o + i];
        sh[o + i] = run;
        run += v;
    }
    if (t == 255) g_blocksum[b] = run;   // block total
    __syncthreads();

#pragma unroll
    for (int i = 0; i < 16; i++) {
        int idx = base + i * 256 + t;
        if (idx < NN) g_rowlocal[idx] = sh[i * 256 + t];
    }

    // last-block computes the 25-entry offset table
    __threadfence();
    __syncthreads();
    if (t == 0) {
        int tk = atomicAdd(&g_done, 1);
        s_last = (tk == SCAN_BLOCKS - 1) ? 1 : 0;
    }
    __syncthreads();
    if (s_last && t == 0) {
        __threadfence();
        int acc = 0;
#pragma unroll
        for (int i = 0; i < SCAN_BLOCKS; i++) {
            int v = *(volatile int*)&g_blocksum[i];
            g_blockoff[i] = acc;
            acc += v;
        }
        g_done = 0;          // reset ticket for next replay
        __threadfence();
    }
}

// ---------------------------------------------------------------------------
// Launch 3: fill CSR slots; pos = rowlocal[r] + blockoff + per-row counter.
// ---------------------------------------------------------------------------
__global__ void fill_kernel(const int*   __restrict__ rows,
                            const int*   __restrict__ cols,
                            const float* __restrict__ vals,
                            const int*   __restrict__ rels,
                            const float* __restrict__ rc)
{
    int e = blockIdx.x * blockDim.x + threadIdx.x;
    if (e >= EE) return;
    int r = rows[e];
    float w = vals[e] / (rc[rels[e]] + 1.0f);
    int pos = g_rowlocal[r] + g_blockoff[r >> 12] + atomicAdd(&g_cnt[r], 1);
    int2 p;
    p.x = cols[e];
    p.y = __float_as_int(w);
    g_cpack[pos] = p;
}

// ---------------------------------------------------------------------------
// Launch 4: SpMM-CSR (R14 config: warp/node, fp32 gather, 8-wide unroll);
// also re-zeroes g_deg/g_cnt for the next graph replay.
// ---------------------------------------------------------------------------
__global__ void __launch_bounds__(256)
spmm_csr_kernel(const float* __restrict__ coeff)
{
    int lane = threadIdx.x & 31;
    int node = blockIdx.x * (blockDim.x >> 5) + (threadIdx.x >> 5);
    if (node >= NN) return;

    int start = g_rowlocal[node] + g_blockoff[node >> 12];
    int end = (node == NN - 1) ? EE
            : g_rowlocal[node + 1] + g_blockoff[(node + 1) >> 12];
    if (lane == 0) {           // reset scratch for next replay
        g_deg[node] = 0;
        g_cnt[node] = 0;
    }

    const float4* hrow = (const float4*)(g_h + (size_t)node * FF);
    float4 hv = hrow[lane];
    float cm = coeff[node] + 1.0f;
    float ax = hv.x * cm, ay = hv.y * cm, az = hv.z * cm, aw = hv.w * cm;

    int p = start;
    for (; p + 8 <= end; p += 8) {
        int2 e0 = g_cpack[p + 0], e1 = g_cpack[p + 1];
        int2 e2 = g_cpack[p + 2], e3 = g_cpack[p + 3];
        int2 e4 = g_cpack[p + 4], e5 = g_cpack[p + 5];
        int2 e6 = g_cpack[p + 6], e7 = g_cpack[p + 7];
        float4 h0 = __ldg(((const float4*)(g_h + (size_t)e0.x * FF)) + lane);
        float4 h1 = __ldg(((const float4*)(g_h + (size_t)e1.x * FF)) + lane);
        float4 h2 = __ldg(((const float4*)(g_h + (size_t)e2.x * FF)) + lane);
        float4 h3 = __ldg(((const float4*)(g_h + (size_t)e3.x * FF)) + lane);
        float4 h4 = __ldg(((const float4*)(g_h + (size_t)e4.x * FF)) + lane);
        float4 h5 = __ldg(((const float4*)(g_h + (size_t)e5.x * FF)) + lane);
        float4 h6 = __ldg(((const float4*)(g_h + (size_t)e6.x * FF)) + lane);
        float4 h7 = __ldg(((const float4*)(g_h + (size_t)e7.x * FF)) + lane);
        float w0 = __int_as_float(e0.y), w1 = __int_as_float(e1.y);
        float w2 = __int_as_float(e2.y), w3 = __int_as_float(e3.y);
        float w4 = __int_as_float(e4.y), w5 = __int_as_float(e5.y);
        float w6 = __int_as_float(e6.y), w7 = __int_as_float(e7.y);
        ax += w0*h0.x + w1*h1.x + w2*h2.x + w3*h3.x + w4*h4.x + w5*h5.x + w6*h6.x + w7*h7.x;
        ay += w0*h0.y + w1*h1.y + w2*h2.y + w3*h3.y + w4*h4.y + w5*h5.y + w6*h6.y + w7*h7.y;
        az += w0*h0.z + w1*h1.z + w2*h2.z + w3*h3.z + w4*h4.z + w5*h5.z + w6*h6.z + w7*h7.z;
        aw += w0*h0.w + w1*h1.w + w2*h2.w + w3*h3.w + w4*h4.w + w5*h5.w + w6*h6.w + w7*h7.w;
    }
    for (; p < end; p++) {
        int2 e0 = g_cpack[p];
        float4 h0 = __ldg(((const float4*)(g_h + (size_t)e0.x * FF)) + lane);
        float w0 = __int_as_float(e0.y);
        ax += w0 * h0.x; ay += w0 * h0.y; az += w0 * h0.z; aw += w0 * h0.w;
    }

    ((float4*)(g_pre + (size_t)node * FF))[lane] = make_float4(ax, ay, az, aw);
}

// ---------------------------------------------------------------------------
// Launch 5: tensor-core GEMM via mma.sync m16n8k16 bf16, 2-way split (R14).
// ---------------------------------------------------------------------------
#define WT_STRIDE 136
#define ROW_BYTES (WT_STRIDE * 2)           // 272
#define SM_AHI 0
#define SM_ALO (SM_AHI + 128 * ROW_BYTES)
#define SM_BHI (SM_ALO + 128 * ROW_BYTES)
#define SM_BLO (SM_BHI + 128 * ROW_BYTES)
#define SM_TOT (SM_BLO + 128 * ROW_BYTES)   // 139264

#define LDSM4(r0, r1, r2, r3, a) \
    asm volatile("ldmatrix.sync.aligned.m8n8.x4.shared.b16 {%0,%1,%2,%3}, [%4];" \
                 : "=r"(r0), "=r"(r1), "=r"(r2), "=r"(r3) : "r"(a))

#define MMA16816(c, a, b) \
    asm volatile("mma.sync.aligned.m16n8k16.row.col.f32.bf16.bf16.f32 " \
                 "{%0,%1,%2,%3}, {%4,%5,%6,%7}, {%8,%9}, {%0,%1,%2,%3};" \
                 : "+f"((c)[0]), "+f"((c)[1]), "+f"((c)[2]), "+f"((c)[3]) \
                 : "r"((a)[0]), "r"((a)[1]), "r"((a)[2]), "r"((a)[3]), \
                   "r"((b)[0]), "r"((b)[1]))

__global__ void __launch_bounds__(256)
gemm_mma_kernel(const float* __restrict__ bias, float* __restrict__ out)
{
    extern __shared__ char smem[];
    uint32_t sb = smem_u32(smem);
    int tid  = threadIdx.x;
    int warp = tid >> 5;
    int lane = tid & 31;
    int row0 = blockIdx.x * 128;

    // B tiles: straight copies
    for (int i = tid; i < 128 * 16; i += 256) {
        int r = i >> 4, c = i & 15;
        *(uint4*)(smem + SM_BHI + r * ROW_BYTES + c * 16) = ((const uint4*)g_wt_hi)[i];
        *(uint4*)(smem + SM_BLO + r * ROW_BYTES + c * 16) = ((const uint4*)g_wt_lo)[i];
    }

    // A convert: thread t -> row t>>1, k-half (t&1)*64
    {
        int lr = tid >> 1;
        int k0 = (tid & 1) * 64;
        int grow = row0 + lr;
        bool valid = (grow < NN);
        const float4* src = (const float4*)(g_pre + (size_t)grow * FF + k0);
        char* dhi = smem + SM_AHI + lr * ROW_BYTES + k0 * 2;
        char* dlo = smem + SM_ALO + lr * ROW_BYTES + k0 * 2;
#pragma unroll
        for (int j = 0; j < 16; j++) {
            float4 v = valid ? __ldg(src + j) : make_float4(0.f, 0.f, 0.f, 0.f);
            float hx = __bfloat162float(__float2bfloat16(v.x));
            float hy = __bfloat162float(__float2bfloat16(v.y));
            float hz = __bfloat162float(__float2bfloat16(v.z));
            float hw = __bfloat162float(__float2bfloat16(v.w));
            *(uint32_t*)(dhi + j * 8)     = pack_bf2(v.x, v.y);
            *(uint32_t*)(dhi + j * 8 + 4) = pack_bf2(v.z, v.w);
            *(uint32_t*)(dlo + j * 8)     = pack_bf2(v.x - hx, v.y - hy);
            *(uint32_t*)(dlo + j * 8 + 4) = pack_bf2(v.z - hz, v.w - hw);
        }
    }
    __syncthreads();

    int wm = warp >> 1;
    int wn = warp & 1;
    int arow = wm * 32;
    int bcol = wn * 64;

    float acc[2][8][4];
#pragma unroll
    for (int mt = 0; mt < 2; mt++)
#pragma unroll
        for (int nt = 0; nt < 8; nt++)
#pragma unroll
            for (int q = 0; q < 4; q++)
                acc[mt][nt][q] = 0.f;

    int a_r = lane & 15;
    int a_c = (lane >> 4) * 8;
    int b_r = ((lane >> 4) << 3) + (lane & 7);
    int b_c = ((lane >> 3) & 1) * 8;

#pragma unroll 1
    for (int ks = 0; ks < 8; ks++) {
        int kk = ks * 16;

        uint32_t ahi[2][4], alo[2][4];
#pragma unroll
        for (int mt = 0; mt < 2; mt++) {
            uint32_t off = (uint32_t)((arow + mt * 16 + a_r) * ROW_BYTES + (kk + a_c) * 2);
            LDSM4(ahi[mt][0], ahi[mt][1], ahi[mt][2], ahi[mt][3], sb + SM_AHI + off);
            LDSM4(alo[mt][0], alo[mt][1], alo[mt][2], alo[mt][3], sb + SM_ALO + off);
        }

        uint32_t bhi[8][2], blo[8][2];
#pragma unroll
        for (int g = 0; g < 4; g++) {
            uint32_t off = (uint32_t)((bcol + g * 16 + b_r) * ROW_BYTES + (kk + b_c) * 2);
            uint32_t r0, r1, r2, r3;
            LDSM4(r0, r1, r2, r3, sb + SM_BHI + off);
            bhi[g * 2 + 0][0] = r0; bhi[g * 2 + 0][1] = r1;
            bhi[g * 2 + 1][0] = r2; bhi[g * 2 + 1][1] = r3;
            LDSM4(r0, r1, r2, r3, sb + SM_BLO + off);
            blo[g * 2 + 0][0] = r0; blo[g * 2 + 0][1] = r1;
            blo[g * 2 + 1][0] = r2; blo[g * 2 + 1][1] = r3;
        }

#pragma unroll
        for (int mt = 0; mt < 2; mt++)
#pragma unroll
            for (int nt = 0; nt < 8; nt++) {
                MMA16816(acc[mt][nt], ahi[mt], bhi[nt]);
                MMA16816(acc[mt][nt], ahi[mt], blo[nt]);
                MMA16816(acc[mt][nt], alo[mt], bhi[nt]);
            }
    }

#pragma unroll
    for (int mt = 0; mt < 2; mt++) {
        int r_lo = row0 + arow + mt * 16 + (lane >> 2);
        int r_hi = r_lo + 8;
#pragma unroll
        for (int nt = 0; nt < 8; nt++) {
            int col = bcol + nt * 8 + (lane & 3) * 2;
            float2 bv = __ldg((const float2*)(bias + col));
            if (r_lo < NN) {
                float2 v0 = make_float2(acc[mt][nt][0] + bv.x, acc[mt][nt][1] + bv.y);
                *(float2*)(out + (size_t)r_lo * FF + col) = v0;
            }
            if (r_hi < NN) {
                float2 v1 = make_float2(acc[mt][nt][2] + bv.x, acc[mt][nt][3] + bv.y);
                *(float2*)(out + (size_t)r_hi * FF + col) = v1;
            }
        }
    }
}

// ---------------------------------------------------------------------------
extern "C" void kernel_launch(void* const* d_in, const int* in_sizes, int n_in,
                              void* d_out, int out_size)
{
    const float* x          = (const float*)d_in[0];
    const int*   edge_rows  = (const int*)  d_in[1];
    const int*   edge_cols  = (const int*)  d_in[2];
    const float* edge_vals  = (const float*)d_in[3];
    const int*   rel_ids    = (const int*)  d_in[4];
    const float* rel_coeffs = (const float*)d_in[5];
    const float* coeff_k    = (const float*)d_in[6];
    const float* dense_W    = (const float*)d_in[7];
    const float* dense_b    = (const float*)d_in[8];
    const float* bn_gamma   = (const float*)d_in[9];
    const float* bn_beta    = (const float*)d_in[10];
    const float* bn_mean    = (const float*)d_in[11];
    const float* bn_var     = (const float*)d_in[12];
    float*       out        = (float*)d_out;

    // 1) fused: BN + W-prep + degree histogram
    fused_front_kernel<<<FUSED_BLOCKS, 256>>>(x, bn_gamma, bn_beta, bn_mean,
                                              bn_var, dense_W, edge_rows);
    // 2) exclusive scan (single launch, last-block offsets)
    scan_kernel<<<SCAN_BLOCKS, 256>>>();
    // 3) CSR fill
    fill_kernel<<<(EE + 255) / 256, 256>>>(edge_rows, edge_cols, edge_vals,
                                           rel_ids, rel_coeffs);
    // 4) SpMM-CSR + coeff residual  (4th launch -> ncu profiles THIS)
    spmm_csr_kernel<<<(NN + 7) / 8, 256>>>(coeff_k);
    // 5) Tensor-core GEMM
    {
        cudaFuncSetAttribute(gemm_mma_kernel,
                             cudaFuncAttributeMaxDynamicSharedMemorySize, SM_TOT);
        gemm_mma_kernel<<<(NN + 127) / 128, 256, SM_TOT>>>(dense_b, out);
    }
}